// round 1
// baseline (speedup 1.0000x reference)
#include <cuda_runtime.h>
#include <cstdint>

// Problem constants (fixed by reference setup)
#define BSZ    4
#define DMODEL 1024
#define SEQL   2048
#define NST    64
#define TCH    128                 // chunk length
#define NC     (SEQL / TCH)        // 16 chunks
#define ROWS   (BSZ * DMODEL)      // 4096 independent rows
#define RC     (ROWS * NC)         // 65536 row-chunks
#define K3K    192                 // 64 (state) + 128 (u chunk)

// -------- device scratch / tables (no allocation allowed in kernel_launch) ----
__device__ float g_A1[NST * TCH];      // GEMM1 A: [i][q] = a_i^(TCH-1-q)   (tf32-rounded)
__device__ float g_M [TCH * K3K];      // GEMM3 A: [p][k] = W|Toeplitz(k)   (tf32-rounded)
__device__ float g_aT[NST];            // a_i^TCH (full fp32, for exact scan)
__device__ float g_loc[(size_t)RC * NST];  // locals  [rc][i]  (16 MB)
__device__ float g_s  [(size_t)RC * NST];  // s_start [rc][i]  (16 MB)

// -------- helpers -------------------------------------------------------------
__device__ __forceinline__ float tf32_rna(float x) {
    uint32_t r;
    asm("cvt.rna.tf32.f32 %0, %1;" : "=r"(r) : "f"(x));
    return __uint_as_float(r);
}

__device__ __forceinline__ void mma_tf32(float c[4], const uint32_t a[4], const uint32_t b[2]) {
    asm volatile(
        "mma.sync.aligned.m16n8k8.row.col.f32.tf32.tf32.f32 "
        "{%0,%1,%2,%3}, {%4,%5,%6,%7}, {%8,%9}, {%0,%1,%2,%3};"
        : "+f"(c[0]), "+f"(c[1]), "+f"(c[2]), "+f"(c[3])
        : "r"(a[0]), "r"(a[1]), "r"(a[2]), "r"(a[3]),
          "r"(b[0]), "r"(b[1]));
}

// ==============================================================================
// Kernel 0: build tables (1 block, 256 threads). Exact fp32 math, then tf32-round
// the GEMM operand tables.
// ==============================================================================
__global__ void k_tables(const float* __restrict__ A,
                         const float* __restrict__ Bv,
                         const float* __restrict__ Cv) {
    __shared__ float P[(TCH + 1) * NST];   // P[p*64+i] = a_i^p, p = 0..128
    __shared__ float sg[NST];
    __shared__ float skk[TCH];
    int t = threadIdx.x;
    if (t < NST) {
        float a = A[t * NST + t];          // diagonal of the dense A parameter
        sg[t] = Bv[t] * Cv[t];
        float pw = 1.f;
        for (int p = 0; p <= TCH; ++p) { P[p * NST + t] = pw; pw *= a; }
        g_aT[t] = P[TCH * NST + t];
    }
    __syncthreads();
    if (t < TCH) {                          // k[m] = sum_i g_i a_i^m
        float s = 0.f;
        for (int i = 0; i < NST; ++i) s += sg[i] * P[t * NST + i];
        skk[t] = s;
    }
    __syncthreads();
    for (int idx = t; idx < NST * TCH; idx += blockDim.x) {
        int i = idx / TCH, q = idx % TCH;
        g_A1[idx] = tf32_rna(P[(TCH - 1 - q) * NST + i]);
    }
    for (int idx = t; idx < TCH * K3K; idx += blockDim.x) {
        int p = idx / K3K, k = idx % K3K;
        float v;
        if (k < NST) {
            v = sg[k] * P[(p + 1) * NST + k];          // W[p][i] = g_i a_i^(p+1)
        } else {
            int q = k - NST;                            // lower-tri Toeplitz k[p-q]
            v = (q <= p) ? skk[p - q] : 0.f;
        }
        g_M[idx] = tf32_rna(v);
    }
}

// ==============================================================================
// Kernel 1: Local(64 x RC) = A1(64x128) @ Uchunks(128 x RC)
// Block tile: 64 x 128 rowchunks. 8 warps, each 32x32 (mma grid 2m x 4n).
// ==============================================================================
__global__ void __launch_bounds__(256, 1)
k_local(const float* __restrict__ u) {
    extern __shared__ float sm[];
    const int SA = 132, SB = 132;          // padded row strides (conflict-free frags)
    float* sA = sm;                        // 64  x 132
    float* sB = sm + 64 * SA;              // 128 x 132 (Bt: [rc][k])
    int tid = threadIdx.x;
    int rc0 = blockIdx.x * 128;

    // stage A (already tf32-rounded): 64*128 floats
    for (int idx = tid; idx < 64 * 32; idx += 256) {
        int m = idx >> 5, j = idx & 31;
        float4 v = reinterpret_cast<const float4*>(g_A1)[m * 32 + j];
        float* d = &sA[m * SA + j * 4];
        d[0] = v.x; d[1] = v.y; d[2] = v.z; d[3] = v.w;
    }
    // stage B: row n holds u[(rc0+n)*128 .. +127] (contiguous), tf32-round
    for (int idx = tid; idx < 128 * 32; idx += 256) {
        int n = idx >> 5, j = idx & 31;
        float4 v = reinterpret_cast<const float4*>(u)[(size_t)(rc0 + n) * 32 + j];
        float* d = &sB[n * SB + j * 4];
        d[0] = tf32_rna(v.x); d[1] = tf32_rna(v.y);
        d[2] = tf32_rna(v.z); d[3] = tf32_rna(v.w);
    }
    __syncthreads();

    int wid = tid >> 5, lane = tid & 31;
    int wm = wid & 1, wn = wid >> 1;       // warp grid 2 (m) x 4 (n)
    int gi = lane >> 2, tg = lane & 3;
    float c[2][4][4] = {};

    #pragma unroll
    for (int k0 = 0; k0 < 128; k0 += 8) {
        uint32_t a[2][4], b[4][2];
        #pragma unroll
        for (int mt = 0; mt < 2; ++mt) {
            const float* pa = &sA[(wm * 32 + mt * 16 + gi) * SA + k0 + tg];
            a[mt][0] = __float_as_uint(pa[0]);
            a[mt][1] = __float_as_uint(pa[8 * SA]);
            a[mt][2] = __float_as_uint(pa[4]);
            a[mt][3] = __float_as_uint(pa[8 * SA + 4]);
        }
        #pragma unroll
        for (int nt = 0; nt < 4; ++nt) {
            const float* pb = &sB[(wn * 32 + nt * 8 + gi) * SB + k0 + tg];
            b[nt][0] = __float_as_uint(pb[0]);
            b[nt][1] = __float_as_uint(pb[4]);
        }
        #pragma unroll
        for (int mt = 0; mt < 2; ++mt)
            #pragma unroll
            for (int nt = 0; nt < 4; ++nt)
                mma_tf32(c[mt][nt], a[mt], b[nt]);
    }

    // epilogue: g_loc[rc*64 + i]
    #pragma unroll
    for (int mt = 0; mt < 2; ++mt)
        #pragma unroll
        for (int nt = 0; nt < 4; ++nt) {
            int i  = wm * 32 + mt * 16 + gi;
            int rc = rc0 + wn * 32 + nt * 8 + 2 * tg;
            g_loc[(size_t)rc * 64 + i]           = c[mt][nt][0];
            g_loc[(size_t)(rc + 1) * 64 + i]     = c[mt][nt][1];
            g_loc[(size_t)rc * 64 + i + 8]       = c[mt][nt][2];
            g_loc[(size_t)(rc + 1) * 64 + i + 8] = c[mt][nt][3];
        }
}

// ==============================================================================
// Kernel 2: exact fp32 scan across chunks. One warp per row, 2 states per lane.
// ==============================================================================
__global__ void k_scan() {
    int gw   = (int)((blockIdx.x * blockDim.x + threadIdx.x) >> 5);  // row
    int lane = threadIdx.x & 31;
    if (gw >= ROWS) return;
    int i0 = lane, i1 = lane + 32;
    float aT0 = g_aT[i0], aT1 = g_aT[i1];
    float s0 = 0.f, s1 = 0.f;
    size_t base = (size_t)gw * NC * 64;
    #pragma unroll
    for (int c = 0; c < NC; ++c) {
        size_t o = base + (size_t)c * 64;
        g_s[o + i0] = s0;
        g_s[o + i1] = s1;
        float l0 = g_loc[o + i0], l1 = g_loc[o + i1];
        s0 = fmaf(aT0, s0, l0);
        s1 = fmaf(aT1, s1, l1);
    }
}

// ==============================================================================
// Kernel 3: Y(128 x RC) = M(128x192) @ [S; Uchunk](192 x RC)
// Block tile: 128 x 64 rowchunks. 8 warps, each 32x32 (warp grid 4m x 2n).
// Output index: y[rc*128 + p] == y[(b,d), c*128 + p]  (exact layout match).
// ==============================================================================
__global__ void __launch_bounds__(256, 1)
k_out(const float* __restrict__ u, float* __restrict__ y) {
    extern __shared__ float sm[];
    const int SA = 196, SB = 196;
    float* sA = sm;                        // 128 x 196
    float* sB = sm + 128 * SA;             // 64  x 196 (Bt: [rc][k]; k<64 = S, k>=64 = u)
    int tid = threadIdx.x;
    int rc0 = blockIdx.x * 64;

    // stage M (already rounded): 128*192 floats = 128*48 float4
    for (int idx = tid; idx < 128 * 48; idx += 256) {
        int m = idx / 48, j = idx % 48;
        float4 v = reinterpret_cast<const float4*>(g_M)[m * 48 + j];
        float* d = &sA[m * SA + j * 4];
        d[0] = v.x; d[1] = v.y; d[2] = v.z; d[3] = v.w;
    }
    // stage S part: 64 rows x 16 float4
    for (int idx = tid; idx < 64 * 16; idx += 256) {
        int n = idx >> 4, j = idx & 15;
        float4 v = reinterpret_cast<const float4*>(g_s)[(size_t)(rc0 + n) * 16 + j];
        float* d = &sB[n * SB + j * 4];
        d[0] = tf32_rna(v.x); d[1] = tf32_rna(v.y);
        d[2] = tf32_rna(v.z); d[3] = tf32_rna(v.w);
    }
    // stage u part: 64 rows x 32 float4 at k-offset 64
    for (int idx = tid; idx < 64 * 32; idx += 256) {
        int n = idx >> 5, j = idx & 31;
        float4 v = reinterpret_cast<const float4*>(u)[(size_t)(rc0 + n) * 32 + j];
        float* d = &sB[n * SB + 64 + j * 4];
        d[0] = tf32_rna(v.x); d[1] = tf32_rna(v.y);
        d[2] = tf32_rna(v.z); d[3] = tf32_rna(v.w);
    }
    __syncthreads();

    int wid = tid >> 5, lane = tid & 31;
    int wm = wid & 3, wn = wid >> 2;       // warp grid 4 (m) x 2 (n)
    int gi = lane >> 2, tg = lane & 3;
    float c[2][4][4] = {};

    #pragma unroll
    for (int k0 = 0; k0 < 192; k0 += 8) {
        uint32_t a[2][4], b[4][2];
        #pragma unroll
        for (int mt = 0; mt < 2; ++mt) {
            const float* pa = &sA[(wm * 32 + mt * 16 + gi) * SA + k0 + tg];
            a[mt][0] = __float_as_uint(pa[0]);
            a[mt][1] = __float_as_uint(pa[8 * SA]);
            a[mt][2] = __float_as_uint(pa[4]);
            a[mt][3] = __float_as_uint(pa[8 * SA + 4]);
        }
        #pragma unroll
        for (int nt = 0; nt < 4; ++nt) {
            const float* pb = &sB[(wn * 32 + nt * 8 + gi) * SB + k0 + tg];
            b[nt][0] = __float_as_uint(pb[0]);
            b[nt][1] = __float_as_uint(pb[4]);
        }
        #pragma unroll
        for (int mt = 0; mt < 2; ++mt)
            #pragma unroll
            for (int nt = 0; nt < 4; ++nt)
                mma_tf32(c[mt][nt], a[mt], b[nt]);
    }

    // epilogue: y[rc*128 + p]
    #pragma unroll
    for (int mt = 0; mt < 2; ++mt)
        #pragma unroll
        for (int nt = 0; nt < 4; ++nt) {
            int p  = wm * 32 + mt * 16 + gi;
            int rc = rc0 + wn * 32 + nt * 8 + 2 * tg;
            y[(size_t)rc * 128 + p]           = c[mt][nt][0];
            y[(size_t)(rc + 1) * 128 + p]     = c[mt][nt][1];
            y[(size_t)rc * 128 + p + 8]       = c[mt][nt][2];
            y[(size_t)(rc + 1) * 128 + p + 8] = c[mt][nt][3];
        }
}

// ==============================================================================
extern "C" void kernel_launch(void* const* d_in, const int* in_sizes, int n_in,
                              void* d_out, int out_size) {
    const float* u  = (const float*)d_in[0];   // (4, 1024, 2048) fp32
    const float* A  = (const float*)d_in[1];   // (64, 64) fp32 (diagonal)
    const float* Bv = (const float*)d_in[2];   // (64,)
    const float* Cv = (const float*)d_in[3];   // (64,)
    float* y = (float*)d_out;                  // (4, 1024, 2048) fp32

    (void)in_sizes; (void)n_in; (void)out_size;

    cudaFuncSetAttribute(k_local, cudaFuncAttributeMaxDynamicSharedMemorySize,
                         (64 + 128) * 132 * 4);
    cudaFuncSetAttribute(k_out, cudaFuncAttributeMaxDynamicSharedMemorySize,
                         (128 + 64) * 196 * 4);

    k_tables<<<1, 256>>>(A, Bv, Cv);
    k_local<<<RC / 128, 256, (64 + 128) * 132 * 4>>>(u);
    k_scan<<<(ROWS * 32) / 256, 256>>>();
    k_out<<<RC / 64, 256, (128 + 64) * 196 * 4>>>(u, y);
}

// round 6
// speedup vs baseline: 1.4854x; 1.4854x over previous
#include <cuda_runtime.h>
#include <cstdint>

// Problem constants (fixed by reference setup)
#define BSZ    4
#define DMODEL 1024
#define SEQL   2048
#define NST    64
#define TCH    128                 // chunk length
#define NC     (SEQL / TCH)        // 16 chunks
#define ROWS   (BSZ * DMODEL)      // 4096 independent rows
#define RC     (ROWS * NC)         // 65536 row-chunks

// Fused-kernel tiling: each block = 8 rows x 16 chunks = 128 row-chunks
#define ROWS_PER_BLK 8
#define RC_BLK       128
#define NBLK         (ROWS / ROWS_PER_BLK)   // 512

// Shared memory layout (floats): u tile + scan buffer only (tables stay global)
#define OFF_U   0                  // u tile: 128 rc x 132 (pad) = 16896 f
#define OFF_AS  16896              // S/loc scan buffer: 128 x 68 = 8704 f
#define SMEM_FLOATS 25600          // = 102400 bytes -> 2 blocks/SM
#define SU_STR  132
#define SS_STR  68

// -------- device tables (built once per launch by k_tables) ------------------
// Permuted so each thread's 4 mma A-regs are one coalesced float4 (512B/warp).
__device__ float4 g_A1p[4 * 16 * 4 * 8];   // 2048 float4 (32.8 KB)
__device__ float4 g_Mp [8 * 24 * 4 * 8];   // 6144 float4 (98.3 KB)
__device__ float  g_aT [NST];              // a_i^128 (full fp32, exact scan)

// -------- helpers -------------------------------------------------------------
__device__ __forceinline__ float tf32_rna(float x) {
    uint32_t r;
    asm("cvt.rna.tf32.f32 %0, %1;" : "=r"(r) : "f"(x));
    return __uint_as_float(r);
}

__device__ __forceinline__ void mma_tf32(float c[4], const uint32_t a[4], const uint32_t b[2]) {
    asm volatile(
        "mma.sync.aligned.m16n8k8.row.col.f32.tf32.tf32.f32 "
        "{%0,%1,%2,%3}, {%4,%5,%6,%7}, {%8,%9}, {%0,%1,%2,%3};"
        : "+f"(c[0]), "+f"(c[1]), "+f"(c[2]), "+f"(c[3])
        : "r"(a[0]), "r"(a[1]), "r"(a[2]), "r"(a[3]),
          "r"(b[0]), "r"(b[1]));
}

// ==============================================================================
// Kernel 0: build permuted operand tables (1 block, 1024 threads).
// A1[i][q] = a_i^(127-q);  M[p][k] = k<64 ? g_k a_k^(p+1) : (q<=p ? kk[p-q] : 0)
// Permutation packs each thread's 4 mma A-regs into one float4:
//   entry((pb,s,tg,gi)) = {X[pb*16+gi][8s+tg], X[pb*16+8+gi][8s+tg],
//                          X[pb*16+gi][8s+4+tg], X[pb*16+8+gi][8s+4+tg]}
// ==============================================================================
__global__ void k_tables(const float* __restrict__ A,
                         const float* __restrict__ Bv,
                         const float* __restrict__ Cv) {
    __shared__ float P[(TCH + 1) * NST];   // P[p*64+i] = a_i^p, p=0..128
    __shared__ float sg[NST];
    __shared__ float skk[TCH];
    int t = threadIdx.x;
    if (t < NST) {
        float a = A[t * NST + t];
        sg[t] = Bv[t] * Cv[t];
        float pw = 1.f;
        for (int p = 0; p <= TCH; ++p) { P[p * NST + t] = pw; pw *= a; }
        g_aT[t] = P[TCH * NST + t];
    }
    __syncthreads();
    if (t < TCH) {
        float s = 0.f;
        for (int i = 0; i < NST; ++i) s += sg[i] * P[t * NST + i];
        skk[t] = s;
    }
    __syncthreads();
    // A1 permuted (4 pb x 16 s x 4 tg x 8 gi)
    for (int e = t; e < 4 * 16 * 4 * 8; e += 1024) {
        int gi = e & 7, r = e >> 3;
        int tg = r & 3; r >>= 2;
        int s  = r & 15; int pb = r >> 4;
        int k0 = 8 * s;
        int i0 = pb * 16 + gi, i1 = i0 + 8;
        float4 v;
        v.x = tf32_rna(P[(127 - (k0 + tg)) * NST + i0]);
        v.y = tf32_rna(P[(127 - (k0 + tg)) * NST + i1]);
        v.z = tf32_rna(P[(127 - (k0 + 4 + tg)) * NST + i0]);
        v.w = tf32_rna(P[(127 - (k0 + 4 + tg)) * NST + i1]);
        g_A1p[e] = v;
    }
    // M permuted (8 pb x 24 s x 4 tg x 8 gi)
    for (int e = t; e < 8 * 24 * 4 * 8; e += 1024) {
        int gi = e & 7, r = e >> 3;
        int tg = r & 3; r >>= 2;
        int s  = r % 24; int pb = r / 24;
        int k0 = 8 * s;
        int p0 = pb * 16 + gi, p1 = p0 + 8;
        auto Mval = [&](int p, int k) -> float {
            float v;
            if (k < NST) v = sg[k] * P[(p + 1) * NST + k];
            else { int q = k - NST; v = (q <= p) ? skk[p - q] : 0.f; }
            return tf32_rna(v);
        };
        float4 v;
        v.x = Mval(p0, k0 + tg);
        v.y = Mval(p1, k0 + tg);
        v.z = Mval(p0, k0 + 4 + tg);
        v.w = Mval(p1, k0 + 4 + tg);
        g_Mp[e] = v;
    }
}

// ==============================================================================
// Fused kernel: per block (8 rows x 2048):
//   1. stage u tile (tf32-rounded) into smem
//   2. Local(64i x 128rc) = A1(64x128) @ U(128 x 128rc)   [A from global/L1]
//   3. in-smem exact fp32 scan over 16 chunks per row
//   4. Y(128p x 128rc) = M(128x192) @ [S(64); U(128)]     [A from global/L1]
// 2 blocks/SM (100 KB smem), 32 warps/SM.
// ==============================================================================
__global__ void __launch_bounds__(512, 2)
k_fused(const float* __restrict__ u, float* __restrict__ y) {
    extern __shared__ float sm[];
    float* sU  = sm + OFF_U;
    float* sAS = sm + OFF_AS;
    const int tid = threadIdx.x;
    const float* gu = u + (size_t)blockIdx.x * (ROWS_PER_BLK * SEQL);
    const float4* __restrict__ pA1 = g_A1p;
    const float4* __restrict__ pM  = g_Mp;

    // ---- stage u tile (tf32-rounded) ----------------------------------------
    for (int e = tid; e < RC_BLK * 32; e += 512) {
        int n = e >> 5, j = e & 31;
        float4 v = reinterpret_cast<const float4*>(gu)[n * 32 + j];
        float* d = &sU[n * SU_STR + j * 4];
        d[0] = tf32_rna(v.x); d[1] = tf32_rna(v.y);
        d[2] = tf32_rna(v.z); d[3] = tf32_rna(v.w);
    }
    __syncthreads();

    const int wid = tid >> 5, lane = tid & 31;
    const int gi = lane >> 2, tg = lane & 3;
    const int wm = wid & 3, wn = wid >> 2;

    // ---- phase 2: local GEMM. Warp tile 16(i) x 32(rc); grid 4m x 4n ---------
    {
        float c[4][4] = {};
        const float* pb0 = &sU[(wn * 32 + gi) * SU_STR + tg];        // nt stride 8*SU_STR
        const float4* pa = &pA1[(wm * 16 * 4 + tg) * 8 + gi];        // s stride 32
        #pragma unroll
        for (int s = 0; s < 16; ++s) {
            uint32_t a[4], b[4][2];
            float4 av = pa[s * 32];
            a[0] = __float_as_uint(av.x); a[1] = __float_as_uint(av.y);
            a[2] = __float_as_uint(av.z); a[3] = __float_as_uint(av.w);
            int k0 = 8 * s;
            #pragma unroll
            for (int nt = 0; nt < 4; ++nt) {
                const float* pb = pb0 + nt * 8 * SU_STR + k0;
                b[nt][0] = __float_as_uint(pb[0]);
                b[nt][1] = __float_as_uint(pb[4]);
            }
            #pragma unroll
            for (int nt = 0; nt < 4; ++nt) mma_tf32(c[nt], a, b[nt]);
        }
        // epilogue: loc -> sAS as [rc][i], stride 68 (sAS not read before here)
        #pragma unroll
        for (int nt = 0; nt < 4; ++nt) {
            int i = wm * 16 + gi;
            int n = wn * 32 + nt * 8 + 2 * tg;
            sAS[n * SS_STR + i]           = c[nt][0];
            sAS[(n + 1) * SS_STR + i]     = c[nt][1];
            sAS[n * SS_STR + i + 8]       = c[nt][2];
            sAS[(n + 1) * SS_STR + i + 8] = c[nt][3];
        }
    }
    __syncthreads();

    // ---- phase 3: exact fp32 scan (warp w owns row w; 2 states per lane) -----
    if (wid < ROWS_PER_BLK) {
        int i0 = lane, i1 = lane + 32;
        float aT0 = __ldg(&g_aT[i0]), aT1 = __ldg(&g_aT[i1]);
        float s0 = 0.f, s1 = 0.f;
        #pragma unroll
        for (int c = 0; c < NC; ++c) {
            int n = wid * NC + c;
            float l0 = sAS[n * SS_STR + i0];
            float l1 = sAS[n * SS_STR + i1];
            sAS[n * SS_STR + i0] = tf32_rna(s0);
            sAS[n * SS_STR + i1] = tf32_rna(s1);
            s0 = fmaf(aT0, s0, l0);
            s1 = fmaf(aT1, s1, l1);
        }
    }
    __syncthreads();

    // ---- phase 4: output GEMM. Warp tile 32(p) x 32(rc); grid 4m x 4n --------
    {
        float c[2][4][4] = {};
        const float*  pbS = &sAS[(wn * 32 + gi) * SS_STR + tg];      // nt stride 8*SS_STR
        const float*  pbU = &sU [(wn * 32 + gi) * SU_STR + tg];
        const float4* pa  = &pM[(wm * 2 * 24 * 4 + tg) * 8 + gi];    // mt stride 24*32, s stride 32
        // K part 1: k in [0,64) -> S from sAS
        #pragma unroll
        for (int s = 0; s < 8; ++s) {
            uint32_t a[2][4], b[4][2];
            int k0 = 8 * s;
            #pragma unroll
            for (int mt = 0; mt < 2; ++mt) {
                float4 av = pa[(mt * 24 + s) * 32];
                a[mt][0] = __float_as_uint(av.x); a[mt][1] = __float_as_uint(av.y);
                a[mt][2] = __float_as_uint(av.z); a[mt][3] = __float_as_uint(av.w);
            }
            #pragma unroll
            for (int nt = 0; nt < 4; ++nt) {
                const float* pb = pbS + nt * 8 * SS_STR + k0;
                b[nt][0] = __float_as_uint(pb[0]);
                b[nt][1] = __float_as_uint(pb[4]);
            }
            #pragma unroll
            for (int mt = 0; mt < 2; ++mt)
                #pragma unroll
                for (int nt = 0; nt < 4; ++nt)
                    mma_tf32(c[mt][nt], a[mt], b[nt]);
        }
        // K part 2: k in [64,192) -> u from sU
        #pragma unroll
        for (int s = 8; s < 24; ++s) {
            uint32_t a[2][4], b[4][2];
            int kk = 8 * s - 64;
            #pragma unroll
            for (int mt = 0; mt < 2; ++mt) {
                float4 av = pa[(mt * 24 + s) * 32];
                a[mt][0] = __float_as_uint(av.x); a[mt][1] = __float_as_uint(av.y);
                a[mt][2] = __float_as_uint(av.z); a[mt][3] = __float_as_uint(av.w);
            }
            #pragma unroll
            for (int nt = 0; nt < 4; ++nt) {
                const float* pb = pbU + nt * 8 * SU_STR + kk;
                b[nt][0] = __float_as_uint(pb[0]);
                b[nt][1] = __float_as_uint(pb[4]);
            }
            #pragma unroll
            for (int mt = 0; mt < 2; ++mt)
                #pragma unroll
                for (int nt = 0; nt < 4; ++nt)
                    mma_tf32(c[mt][nt], a[mt], b[nt]);
        }
        // epilogue: y[(rc)*128 + p]
        size_t rcbase = (size_t)blockIdx.x * RC_BLK;
        #pragma unroll
        for (int mt = 0; mt < 2; ++mt)
            #pragma unroll
            for (int nt = 0; nt < 4; ++nt) {
                int p = wm * 32 + mt * 16 + gi;
                size_t rc = rcbase + wn * 32 + nt * 8 + 2 * tg;
                y[rc * 128 + p]             = c[mt][nt][0];
                y[(rc + 1) * 128 + p]       = c[mt][nt][1];
                y[rc * 128 + p + 8]         = c[mt][nt][2];
                y[(rc + 1) * 128 + p + 8]   = c[mt][nt][3];
            }
    }
}

// ==============================================================================
extern "C" void kernel_launch(void* const* d_in, const int* in_sizes, int n_in,
                              void* d_out, int out_size) {
    const float* u  = (const float*)d_in[0];   // (4, 1024, 2048) fp32
    const float* A  = (const float*)d_in[1];   // (64, 64) fp32 (diagonal)
    const float* Bv = (const float*)d_in[2];   // (64,)
    const float* Cv = (const float*)d_in[3];   // (64,)
    float* y = (float*)d_out;                  // (4, 1024, 2048) fp32

    (void)in_sizes; (void)n_in; (void)out_size;

    cudaFuncSetAttribute(k_fused, cudaFuncAttributeMaxDynamicSharedMemorySize,
                         SMEM_FLOATS * 4);

    k_tables<<<1, 1024>>>(A, Bv, Cv);
    k_fused<<<NBLK, 512, SMEM_FLOATS * 4>>>(u, y);
}

// round 7
// speedup vs baseline: 2.3532x; 1.5843x over previous
#include <cuda_runtime.h>
#include <cuda_fp16.h>
#include <cstdint>

// Problem constants (fixed by reference setup)
#define BSZ    4
#define DMODEL 1024
#define SEQL   2048
#define NST    64
#define TCH    128                 // chunk length
#define NC     (SEQL / TCH)        // 16 chunks
#define ROWS   (BSZ * DMODEL)      // 4096 independent rows
#define RC     (ROWS * NC)         // 65536 row-chunks

// Fused-kernel tiling: each block = 8 rows x 16 chunks = 128 row-chunks
#define ROWS_PER_BLK 8
#define RC_BLK       128
#define NBLK         (ROWS / ROWS_PER_BLK)   // 512

// Shared memory layout (bytes):
//   sU  (half):  128 rc x 136 (k=128 + pad8)  = 34816 B
//   sAS (float): 128 rc x 68  (Local, fp32)   = 34816 B
//   sS  (half):  128 rc x 72  (S states fp16) = 18432 B
#define OFF_U_B   0
#define OFF_AS_B  34816
#define OFF_S_B   69632
#define SMEM_BYTES 88064           // x2 blocks/SM = 176 KB < 227 KB
#define SU_STR  136                // halves
#define SS_STR  68                 // floats
#define ST_STR  72                 // halves

// -------- device tables (built once per launch by k_tables) ------------------
// fp16 permuted A-operand tables: each thread's 4 mma A-regs = one uint4.
// entry(tile,s,tg,gi): x={X[m0][k0+2tg],X[m0][k0+2tg+1]}, y={X[m1][..]},
//                      z={X[m0][k0+2tg+8],+9}, w={X[m1][k0+2tg+8],+9}
// with m0=tile*16+gi, m1=m0+8, k0=16*s.
__device__ uint4 g_A1h[4 * 8 * 4 * 8];    // A1: 64i x 128k  (16 KB)
__device__ uint4 g_Mh [8 * 12 * 4 * 8];   // M: 128p x 192k  (48 KB)
__device__ float g_aT [NST];              // a_i^128 (full fp32, exact scan)

// -------- helpers -------------------------------------------------------------
__device__ __forceinline__ uint32_t h2(float a, float b) {
    __half2 h = __floats2half2_rn(a, b);   // low half = a (k even), high = b
    return *reinterpret_cast<uint32_t*>(&h);
}

__device__ __forceinline__ void mma_f16(float c[4], uint4 a, uint32_t b0, uint32_t b1) {
    asm volatile(
        "mma.sync.aligned.m16n8k16.row.col.f32.f16.f16.f32 "
        "{%0,%1,%2,%3}, {%4,%5,%6,%7}, {%8,%9}, {%0,%1,%2,%3};"
        : "+f"(c[0]), "+f"(c[1]), "+f"(c[2]), "+f"(c[3])
        : "r"(a.x), "r"(a.y), "r"(a.z), "r"(a.w), "r"(b0), "r"(b1));
}

// ==============================================================================
// Kernel 0: build fp16 permuted operand tables (1 block, 1024 threads).
// A1[i][q] = a_i^(127-q);  M[p][k] = k<64 ? g_k a_k^(p+1) : (q<=p ? kk[p-q] : 0)
// ==============================================================================
__global__ void k_tables(const float* __restrict__ A,
                         const float* __restrict__ Bv,
                         const float* __restrict__ Cv) {
    __shared__ float P[(TCH + 1) * NST];   // P[p*64+i] = a_i^p, p=0..128
    __shared__ float sg[NST];
    __shared__ float skk[TCH];
    int t = threadIdx.x;
    if (t < NST) {
        float a = A[t * NST + t];
        sg[t] = Bv[t] * Cv[t];
        float pw = 1.f;
        for (int p = 0; p <= TCH; ++p) { P[p * NST + t] = pw; pw *= a; }
        g_aT[t] = P[TCH * NST + t];
    }
    __syncthreads();
    if (t < TCH) {
        float s = 0.f;
        for (int i = 0; i < NST; ++i) s += sg[i] * P[t * NST + i];
        skk[t] = s;
    }
    __syncthreads();
    // A1 table: (it 0..3, s 0..7, tg 0..3, gi 0..7)
    for (int e = t; e < 4 * 8 * 4 * 8; e += 1024) {
        int gi = e & 7, r = e >> 3;
        int tg = r & 3; r >>= 2;
        int s  = r & 7; int it = r >> 3;
        int i0 = it * 16 + gi, i1 = i0 + 8;
        int k0 = 16 * s;
        auto A1v = [&](int i, int q) -> float { return P[(127 - q) * NST + i]; };
        uint4 v;
        v.x = h2(A1v(i0, k0 + 2 * tg),     A1v(i0, k0 + 2 * tg + 1));
        v.y = h2(A1v(i1, k0 + 2 * tg),     A1v(i1, k0 + 2 * tg + 1));
        v.z = h2(A1v(i0, k0 + 2 * tg + 8), A1v(i0, k0 + 2 * tg + 9));
        v.w = h2(A1v(i1, k0 + 2 * tg + 8), A1v(i1, k0 + 2 * tg + 9));
        g_A1h[e] = v;
    }
    // M table: (tp 0..7, s 0..11, tg, gi)
    for (int e = t; e < 8 * 12 * 4 * 8; e += 1024) {
        int gi = e & 7, r = e >> 3;
        int tg = r & 3; r >>= 2;
        int s  = r % 12; int tp = r / 12;
        int p0 = tp * 16 + gi, p1 = p0 + 8;
        int k0 = 16 * s;
        auto Mval = [&](int p, int k) -> float {
            if (k < NST) return sg[k] * P[(p + 1) * NST + k];
            int q = k - NST;
            return (q <= p) ? skk[p - q] : 0.f;
        };
        uint4 v;
        v.x = h2(Mval(p0, k0 + 2 * tg),     Mval(p0, k0 + 2 * tg + 1));
        v.y = h2(Mval(p1, k0 + 2 * tg),     Mval(p1, k0 + 2 * tg + 1));
        v.z = h2(Mval(p0, k0 + 2 * tg + 8), Mval(p0, k0 + 2 * tg + 9));
        v.w = h2(Mval(p1, k0 + 2 * tg + 8), Mval(p1, k0 + 2 * tg + 9));
        g_Mh[e] = v;
    }
}

// ==============================================================================
// Fused kernel: per block (8 rows x 2048):
//   1. stage u tile as fp16 into smem
//   2. Local(64i x 128rc) = A1 @ U            [fp16 mma, fp32 acc -> sAS fp32]
//   3. exact fp32 scan over 16 chunks/row; S stored fp16 -> sS
//   4. Y(128p x 128rc) = M @ [S; U]           [fp16 mma, fp32 acc -> y]
// 2 blocks/SM (88 KB smem), 32 warps/SM.
// ==============================================================================
__global__ void __launch_bounds__(512, 2)
k_fused(const float* __restrict__ u, float* __restrict__ y) {
    extern __shared__ char smem[];
    __half* sUh = reinterpret_cast<__half*>(smem + OFF_U_B);
    float*  sAS = reinterpret_cast<float*>(smem + OFF_AS_B);
    __half* sSh = reinterpret_cast<__half*>(smem + OFF_S_B);
    const int tid = threadIdx.x;
    const float* gu = u + (size_t)blockIdx.x * (ROWS_PER_BLK * SEQL);
    const uint4* __restrict__ pA1 = g_A1h;
    const uint4* __restrict__ pM  = g_Mh;

    // ---- stage u tile as fp16 ------------------------------------------------
    for (int e = tid; e < RC_BLK * 32; e += 512) {
        int n = e >> 5, j = e & 31;
        float4 v = reinterpret_cast<const float4*>(gu)[n * 32 + j];
        uint2 w;
        w.x = h2(v.x, v.y);
        w.y = h2(v.z, v.w);
        *reinterpret_cast<uint2*>(&sUh[n * SU_STR + 4 * j]) = w;
    }
    __syncthreads();

    const int wid = tid >> 5, lane = tid & 31;
    const int gi = lane >> 2, tg = lane & 3;
    const int wm = wid & 3, wn = wid >> 2;

    // ---- phase 2: local GEMM. Warp tile 16(i) x 32(rc); grid 4m x 4n ---------
    {
        float c[4][4] = {};
        const uint4*  pa  = pA1 + wm * 256 + tg * 8 + gi;              // s stride 32
        const __half* pb0 = &sUh[(wn * 32 + gi) * SU_STR + 2 * tg];    // nt stride 8*SU_STR
        #pragma unroll
        for (int s = 0; s < 8; ++s) {
            uint4 av = pa[s * 32];
            int k0 = 16 * s;
            uint32_t b[4][2];
            #pragma unroll
            for (int nt = 0; nt < 4; ++nt) {
                const __half* pb = pb0 + nt * 8 * SU_STR + k0;
                b[nt][0] = *reinterpret_cast<const uint32_t*>(pb);
                b[nt][1] = *reinterpret_cast<const uint32_t*>(pb + 8);
            }
            #pragma unroll
            for (int nt = 0; nt < 4; ++nt) mma_f16(c[nt], av, b[nt][0], b[nt][1]);
        }
        // epilogue: Local (fp32) -> sAS as [rc][i], stride 68
        #pragma unroll
        for (int nt = 0; nt < 4; ++nt) {
            int i = wm * 16 + gi;
            int n = wn * 32 + nt * 8 + 2 * tg;
            sAS[n * SS_STR + i]           = c[nt][0];
            sAS[(n + 1) * SS_STR + i]     = c[nt][1];
            sAS[n * SS_STR + i + 8]       = c[nt][2];
            sAS[(n + 1) * SS_STR + i + 8] = c[nt][3];
        }
    }
    __syncthreads();

    // ---- phase 3: exact fp32 scan; S output rounded to fp16 ------------------
    if (wid < ROWS_PER_BLK) {
        int i0 = lane, i1 = lane + 32;
        float aT0 = __ldg(&g_aT[i0]), aT1 = __ldg(&g_aT[i1]);
        float s0 = 0.f, s1 = 0.f;
        #pragma unroll
        for (int c = 0; c < NC; ++c) {
            int n = wid * NC + c;
            float l0 = sAS[n * SS_STR + i0];
            float l1 = sAS[n * SS_STR + i1];
            sSh[n * ST_STR + i0] = __float2half_rn(s0);
            sSh[n * ST_STR + i1] = __float2half_rn(s1);
            s0 = fmaf(aT0, s0, l0);
            s1 = fmaf(aT1, s1, l1);
        }
    }
    __syncthreads();

    // ---- phase 4: output GEMM. Warp tile 32(p) x 32(rc); grid 4m x 4n --------
    {
        float c[2][4][4] = {};
        const __half* pbS = &sSh[(wn * 32 + gi) * ST_STR + 2 * tg];    // nt stride 8*ST_STR
        const __half* pbU = &sUh[(wn * 32 + gi) * SU_STR + 2 * tg];
        const uint4*  pa  = pM + (wm * 2) * 384 + tg * 8 + gi;         // mt stride 384, s stride 32
        // K part 1: s=0..3 -> S from sSh (k = 16s)
        #pragma unroll
        for (int s = 0; s < 4; ++s) {
            uint4 a0 = pa[s * 32];
            uint4 a1 = pa[384 + s * 32];
            int k0 = 16 * s;
            uint32_t b[4][2];
            #pragma unroll
            for (int nt = 0; nt < 4; ++nt) {
                const __half* pb = pbS + nt * 8 * ST_STR + k0;
                b[nt][0] = *reinterpret_cast<const uint32_t*>(pb);
                b[nt][1] = *reinterpret_cast<const uint32_t*>(pb + 8);
            }
            #pragma unroll
            for (int nt = 0; nt < 4; ++nt) {
                mma_f16(c[0][nt], a0, b[nt][0], b[nt][1]);
                mma_f16(c[1][nt], a1, b[nt][0], b[nt][1]);
            }
        }
        // K part 2: s=4..11 -> u from sUh (kk = 16s - 64)
        #pragma unroll
        for (int s = 4; s < 12; ++s) {
            uint4 a0 = pa[s * 32];
            uint4 a1 = pa[384 + s * 32];
            int kk = 16 * s - 64;
            uint32_t b[4][2];
            #pragma unroll
            for (int nt = 0; nt < 4; ++nt) {
                const __half* pb = pbU + nt * 8 * SU_STR + kk;
                b[nt][0] = *reinterpret_cast<const uint32_t*>(pb);
                b[nt][1] = *reinterpret_cast<const uint32_t*>(pb + 8);
            }
            #pragma unroll
            for (int nt = 0; nt < 4; ++nt) {
                mma_f16(c[0][nt], a0, b[nt][0], b[nt][1]);
                mma_f16(c[1][nt], a1, b[nt][0], b[nt][1]);
            }
        }
        // epilogue: y[(rc)*128 + p]
        size_t rcbase = (size_t)blockIdx.x * RC_BLK;
        #pragma unroll
        for (int mt = 0; mt < 2; ++mt)
            #pragma unroll
            for (int nt = 0; nt < 4; ++nt) {
                int p = wm * 32 + mt * 16 + gi;
                size_t rc = rcbase + wn * 32 + nt * 8 + 2 * tg;
                y[rc * 128 + p]             = c[mt][nt][0];
                y[(rc + 1) * 128 + p]       = c[mt][nt][1];
                y[rc * 128 + p + 8]         = c[mt][nt][2];
                y[(rc + 1) * 128 + p + 8]   = c[mt][nt][3];
            }
    }
}

// ==============================================================================
extern "C" void kernel_launch(void* const* d_in, const int* in_sizes, int n_in,
                              void* d_out, int out_size) {
    const float* u  = (const float*)d_in[0];   // (4, 1024, 2048) fp32
    const float* A  = (const float*)d_in[1];   // (64, 64) fp32 (diagonal)
    const float* Bv = (const float*)d_in[2];   // (64,)
    const float* Cv = (const float*)d_in[3];   // (64,)
    float* y = (float*)d_out;                  // (4, 1024, 2048) fp32

    (void)in_sizes; (void)n_in; (void)out_size;

    cudaFuncSetAttribute(k_fused, cudaFuncAttributeMaxDynamicSharedMemorySize,
                         SMEM_BYTES);

    k_tables<<<1, 1024>>>(A, Bv, Cv);
    k_fused<<<NBLK, 512, SMEM_BYTES>>>(u, y);
}

// round 8
// speedup vs baseline: 2.4896x; 1.0579x over previous
#include <cuda_runtime.h>
#include <cuda_fp16.h>
#include <cstdint>

// Problem constants (fixed by reference setup)
#define BSZ    4
#define DMODEL 1024
#define SEQL   2048
#define NST    64
#define TCH    128                 // chunk length
#define NC     (SEQL / TCH)        // 16 chunks
#define ROWS   (BSZ * DMODEL)      // 4096 independent rows
#define RC     (ROWS * NC)         // 65536 row-chunks

// Fused-kernel tiling: each block = 8 rows x 16 chunks = 128 row-chunks
#define ROWS_PER_BLK 8
#define RC_BLK       128
#define NBLK         (ROWS / ROWS_PER_BLK)   // 512

// Shared memory layout (bytes):
//   sU  (half):  128 rc x 136 (k=128 + pad8)  = 34816 B
//   sAS (float): 128 rc x 68  (Local, fp32)   = 34816 B
//   sS  (half):  128 rc x 72  (S states fp16) = 18432 B
#define OFF_U_B   0
#define OFF_AS_B  34816
#define OFF_S_B   69632
#define SMEM_BYTES 88064           // x2 blocks/SM = 176 KB < 227 KB
#define SU_STR  136                // halves
#define SS_STR  68                 // floats
#define ST_STR  72                 // halves

// -------- device tables (built once per launch by k_tables) ------------------
// fp16 permuted A-operand tables: each thread's 4 mma A-regs = one uint4.
// entry(tile,s,tg,gi): x={X[m0][k0+2tg],X[m0][k0+2tg+1]}, y={X[m1][..]},
//                      z={X[m0][k0+2tg+8],+9}, w={X[m1][k0+2tg+8],+9}
// with m0=tile*16+gi, m1=m0+8, k0=16*s.
__device__ uint4 g_A1h[4 * 8 * 4 * 8];    // A1: 64i x 128k  (16 KB)
__device__ uint4 g_Mh [8 * 12 * 4 * 8];   // M: 128p x 192k  (48 KB)
__device__ float g_aT [NST];              // a_i^128 (full fp32, exact scan)

// -------- helpers -------------------------------------------------------------
__device__ __forceinline__ uint32_t h2(float a, float b) {
    __half2 h = __floats2half2_rn(a, b);   // low half = a (k even), high = b
    return *reinterpret_cast<uint32_t*>(&h);
}

__device__ __forceinline__ void mma_f16(float c[4], uint4 a, uint32_t b0, uint32_t b1) {
    asm volatile(
        "mma.sync.aligned.m16n8k16.row.col.f32.f16.f16.f32 "
        "{%0,%1,%2,%3}, {%4,%5,%6,%7}, {%8,%9}, {%0,%1,%2,%3};"
        : "+f"(c[0]), "+f"(c[1]), "+f"(c[2]), "+f"(c[3])
        : "r"(a.x), "r"(a.y), "r"(a.z), "r"(a.w), "r"(b0), "r"(b1));
}

// ==============================================================================
// Kernel 0: build fp16 permuted operand tables (1 block, 1024 threads).
// A1[i][q] = a_i^(127-q);  M[p][k] = k<64 ? g_k a_k^(p+1) : (q<=p ? kk[p-q] : 0)
// ==============================================================================
__global__ void k_tables(const float* __restrict__ A,
                         const float* __restrict__ Bv,
                         const float* __restrict__ Cv) {
    __shared__ float P[(TCH + 1) * NST];   // P[p*64+i] = a_i^p, p=0..128
    __shared__ float sg[NST];
    __shared__ float skk[TCH];
    int t = threadIdx.x;
    if (t < NST) {
        float a = A[t * NST + t];
        sg[t] = Bv[t] * Cv[t];
        float pw = 1.f;
        for (int p = 0; p <= TCH; ++p) { P[p * NST + t] = pw; pw *= a; }
        g_aT[t] = P[TCH * NST + t];
    }
    __syncthreads();
    if (t < TCH) {
        float s = 0.f;
        for (int i = 0; i < NST; ++i) s += sg[i] * P[t * NST + i];
        skk[t] = s;
    }
    __syncthreads();
    // A1 table: (it 0..3, s 0..7, tg 0..3, gi 0..7)
    for (int e = t; e < 4 * 8 * 4 * 8; e += 1024) {
        int gi = e & 7, r = e >> 3;
        int tg = r & 3; r >>= 2;
        int s  = r & 7; int it = r >> 3;
        int i0 = it * 16 + gi, i1 = i0 + 8;
        int k0 = 16 * s;
        auto A1v = [&](int i, int q) -> float { return P[(127 - q) * NST + i]; };
        uint4 v;
        v.x = h2(A1v(i0, k0 + 2 * tg),     A1v(i0, k0 + 2 * tg + 1));
        v.y = h2(A1v(i1, k0 + 2 * tg),     A1v(i1, k0 + 2 * tg + 1));
        v.z = h2(A1v(i0, k0 + 2 * tg + 8), A1v(i0, k0 + 2 * tg + 9));
        v.w = h2(A1v(i1, k0 + 2 * tg + 8), A1v(i1, k0 + 2 * tg + 9));
        g_A1h[e] = v;
    }
    // M table: (tp 0..7, s 0..11, tg, gi)
    for (int e = t; e < 8 * 12 * 4 * 8; e += 1024) {
        int gi = e & 7, r = e >> 3;
        int tg = r & 3; r >>= 2;
        int s  = r % 12; int tp = r / 12;
        int p0 = tp * 16 + gi, p1 = p0 + 8;
        int k0 = 16 * s;
        auto Mval = [&](int p, int k) -> float {
            if (k < NST) return sg[k] * P[(p + 1) * NST + k];
            int q = k - NST;
            return (q <= p) ? skk[p - q] : 0.f;
        };
        uint4 v;
        v.x = h2(Mval(p0, k0 + 2 * tg),     Mval(p0, k0 + 2 * tg + 1));
        v.y = h2(Mval(p1, k0 + 2 * tg),     Mval(p1, k0 + 2 * tg + 1));
        v.z = h2(Mval(p0, k0 + 2 * tg + 8), Mval(p0, k0 + 2 * tg + 9));
        v.w = h2(Mval(p1, k0 + 2 * tg + 8), Mval(p1, k0 + 2 * tg + 9));
        g_Mh[e] = v;
    }
}

// ==============================================================================
// Fused kernel: per block (8 rows x 2048):
//   1. stage u tile as fp16 into smem
//   2. Local(64i x 128rc) = A1 @ U            [fp16 mma, fp32 acc -> sAS fp32]
//   3. exact fp32 scan over 16 chunks/row; S stored fp16 -> sS
//   4. Y(128p x 128rc) = M @ [S; U] with triangular skip on the Toeplitz block
// 2 blocks/SM (88 KB smem), 32 warps/SM.
// ==============================================================================
__global__ void __launch_bounds__(512, 2)
k_fused(const float* __restrict__ u, float* __restrict__ y) {
    extern __shared__ char smem[];
    __half* sUh = reinterpret_cast<__half*>(smem + OFF_U_B);
    float*  sAS = reinterpret_cast<float*>(smem + OFF_AS_B);
    __half* sSh = reinterpret_cast<__half*>(smem + OFF_S_B);
    const int tid = threadIdx.x;
    const float* gu = u + (size_t)blockIdx.x * (ROWS_PER_BLK * SEQL);
    const uint4* __restrict__ pA1 = g_A1h;
    const uint4* __restrict__ pM  = g_Mh;

    // ---- stage u tile as fp16 ------------------------------------------------
    for (int e = tid; e < RC_BLK * 32; e += 512) {
        int n = e >> 5, j = e & 31;
        float4 v = reinterpret_cast<const float4*>(gu)[n * 32 + j];
        uint2 w;
        w.x = h2(v.x, v.y);
        w.y = h2(v.z, v.w);
        *reinterpret_cast<uint2*>(&sUh[n * SU_STR + 4 * j]) = w;
    }
    __syncthreads();

    const int wid = tid >> 5, lane = tid & 31;
    const int gi = lane >> 2, tg = lane & 3;
    const int wm = wid & 3, wn = wid >> 2;

    // ---- phase 2: local GEMM. Warp tile 16(i) x 32(rc); grid 4m x 4n ---------
    {
        float c[4][4] = {};
        const uint4*  pa  = pA1 + wm * 256 + tg * 8 + gi;              // s stride 32
        const __half* pb0 = &sUh[(wn * 32 + gi) * SU_STR + 2 * tg];    // nt stride 8*SU_STR
        #pragma unroll
        for (int s = 0; s < 8; ++s) {
            uint4 av = pa[s * 32];
            int k0 = 16 * s;
            uint32_t b[4][2];
            #pragma unroll
            for (int nt = 0; nt < 4; ++nt) {
                const __half* pb = pb0 + nt * 8 * SU_STR + k0;
                b[nt][0] = *reinterpret_cast<const uint32_t*>(pb);
                b[nt][1] = *reinterpret_cast<const uint32_t*>(pb + 8);
            }
            #pragma unroll
            for (int nt = 0; nt < 4; ++nt) mma_f16(c[nt], av, b[nt][0], b[nt][1]);
        }
        // epilogue: Local (fp32) -> sAS as [rc][i], stride 68
        #pragma unroll
        for (int nt = 0; nt < 4; ++nt) {
            int i = wm * 16 + gi;
            int n = wn * 32 + nt * 8 + 2 * tg;
            sAS[n * SS_STR + i]           = c[nt][0];
            sAS[(n + 1) * SS_STR + i]     = c[nt][1];
            sAS[n * SS_STR + i + 8]       = c[nt][2];
            sAS[(n + 1) * SS_STR + i + 8] = c[nt][3];
        }
    }
    __syncthreads();

    // ---- phase 3: exact fp32 scan; S output rounded to fp16 ------------------
    if (wid < ROWS_PER_BLK) {
        int i0 = lane, i1 = lane + 32;
        float aT0 = __ldg(&g_aT[i0]), aT1 = __ldg(&g_aT[i1]);
        float s0 = 0.f, s1 = 0.f;
        #pragma unroll
        for (int c = 0; c < NC; ++c) {
            int n = wid * NC + c;
            float l0 = sAS[n * SS_STR + i0];
            float l1 = sAS[n * SS_STR + i1];
            sSh[n * ST_STR + i0] = __float2half_rn(s0);
            sSh[n * ST_STR + i1] = __float2half_rn(s1);
            s0 = fmaf(aT0, s0, l0);
            s1 = fmaf(aT1, s1, l1);
        }
    }
    __syncthreads();

    // ---- phase 4: output GEMM, balanced triangular skip ----------------------
    // Warp wm owns p-tiles {wm, 7-wm} (16 rows each); grid 4(pairs) x 4(rc).
    // Toeplitz block: tile t only needs u-steps s <= t+4 (rest exactly zero).
    {
        float c[2][4][4] = {};
        const int t0 = wm;                 // active u-steps: s <= 4+wm
        const int t1 = 7 - wm;             // active u-steps: s <= 11-wm (superset)
        const __half* pbS = &sSh[(wn * 32 + gi) * ST_STR + 2 * tg];    // nt stride 8*ST_STR
        const __half* pbU = &sUh[(wn * 32 + gi) * SU_STR + 2 * tg];
        const uint4*  pa0 = pM + t0 * 384 + tg * 8 + gi;               // s stride 32
        const uint4*  pa1 = pM + t1 * 384 + tg * 8 + gi;
        // K part 1: s=0..3 -> S from sSh (dense W block, both tiles)
        #pragma unroll
        for (int s = 0; s < 4; ++s) {
            uint4 a0 = pa0[s * 32];
            uint4 a1 = pa1[s * 32];
            int k0 = 16 * s;
            uint32_t b[4][2];
            #pragma unroll
            for (int nt = 0; nt < 4; ++nt) {
                const __half* pb = pbS + nt * 8 * ST_STR + k0;
                b[nt][0] = *reinterpret_cast<const uint32_t*>(pb);
                b[nt][1] = *reinterpret_cast<const uint32_t*>(pb + 8);
            }
            #pragma unroll
            for (int nt = 0; nt < 4; ++nt) {
                mma_f16(c[0][nt], a0, b[nt][0], b[nt][1]);
                mma_f16(c[1][nt], a1, b[nt][0], b[nt][1]);
            }
        }
        // K part 2: s=4..11 -> u from sUh; skip all-zero Toeplitz MMAs
        #pragma unroll
        for (int s = 4; s < 12; ++s) {
            if (s <= 11 - wm) {            // tile t1 active (warp-uniform)
                int kk = 16 * s - 64;
                uint32_t b[4][2];
                #pragma unroll
                for (int nt = 0; nt < 4; ++nt) {
                    const __half* pb = pbU + nt * 8 * SU_STR + kk;
                    b[nt][0] = *reinterpret_cast<const uint32_t*>(pb);
                    b[nt][1] = *reinterpret_cast<const uint32_t*>(pb + 8);
                }
                uint4 a1 = pa1[s * 32];
                #pragma unroll
                for (int nt = 0; nt < 4; ++nt)
                    mma_f16(c[1][nt], a1, b[nt][0], b[nt][1]);
                if (s <= 4 + wm) {         // tile t0 active (subset of t1 range)
                    uint4 a0 = pa0[s * 32];
                    #pragma unroll
                    for (int nt = 0; nt < 4; ++nt)
                        mma_f16(c[0][nt], a0, b[nt][0], b[nt][1]);
                }
            }
        }
        // epilogue: y[(rc)*128 + p], tile mt=0 -> p-tile t0, mt=1 -> t1
        size_t rcbase = (size_t)blockIdx.x * RC_BLK;
        #pragma unroll
        for (int mt = 0; mt < 2; ++mt) {
            int pbase = (mt == 0 ? t0 : t1) * 16 + gi;
            #pragma unroll
            for (int nt = 0; nt < 4; ++nt) {
                size_t rc = rcbase + wn * 32 + nt * 8 + 2 * tg;
                y[rc * 128 + pbase]           = c[mt][nt][0];
                y[(rc + 1) * 128 + pbase]     = c[mt][nt][1];
                y[rc * 128 + pbase + 8]       = c[mt][nt][2];
                y[(rc + 1) * 128 + pbase + 8] = c[mt][nt][3];
            }
        }
    }
}

// ==============================================================================
extern "C" void kernel_launch(void* const* d_in, const int* in_sizes, int n_in,
                              void* d_out, int out_size) {
    const float* u  = (const float*)d_in[0];   // (4, 1024, 2048) fp32
    const float* A  = (const float*)d_in[1];   // (64, 64) fp32 (diagonal)
    const float* Bv = (const float*)d_in[2];   // (64,)
    const float* Cv = (const float*)d_in[3];   // (64,)
    float* y = (float*)d_out;                  // (4, 1024, 2048) fp32

    (void)in_sizes; (void)n_in; (void)out_size;

    cudaFuncSetAttribute(k_fused, cudaFuncAttributeMaxDynamicSharedMemorySize,
                         SMEM_BYTES);

    k_tables<<<1, 1024>>>(A, Bv, Cv);
    k_fused<<<NBLK, 512, SMEM_BYTES>>>(u, y);
}